// round 1
// baseline (speedup 1.0000x reference)
#include <cuda_runtime.h>
#include <cuda_fp16.h>
#include <cstdint>

// ---------------- problem constants ----------------
#define HID   512
#define G4    2048         // 4*HID
#define NAg   64           // agents
#define NTr   32           // trajectories
#define SEQ   16
#define BROWS 2048         // NTr*NAg rows per timestep
#define TROWS 32768        // SEQ*BROWS
#define NATTN 256
#define OUTHALF 16777216   // 512*64*512

#define AS 72              // smem tile row stride (halves)
#define DS 132             // Dsm row stride (floats)

// ---------------- scratch (static device allocations are the sanctioned path) ----
__device__ __half g_Wih_h[G4 * HID];
__device__ __half g_Whh_h[G4 * HID];
__device__ float  g_bsum[G4];
__device__ __half g_Xh[(size_t)TROWS * HID];          // 32 MB packed time-major x (fp16)
__device__ float  g_Gx[(size_t)TROWS * G4];           // 256 MB precomputed x-gates (fp32)
__device__ float  g_hbuf[2][BROWS * HID];             // double-buffered carry
__device__ float  g_cbuf[2][BROWS * HID];

// ---------------- helpers ----------------
__device__ __forceinline__ void mma16816(float* d, const uint32_t* a, uint32_t b0, uint32_t b1) {
    asm volatile(
        "mma.sync.aligned.m16n8k16.row.col.f32.f16.f16.f32 "
        "{%0,%1,%2,%3},{%4,%5,%6,%7},{%8,%9},{%0,%1,%2,%3};\n"
        : "+f"(d[0]), "+f"(d[1]), "+f"(d[2]), "+f"(d[3])
        : "r"(a[0]), "r"(a[1]), "r"(a[2]), "r"(a[3]), "r"(b0), "r"(b1));
}

__device__ __forceinline__ float sigmoid_f(float x) { return 1.f / (1.f + __expf(-x)); }
// tanh via exp2-based fast exp; saturates correctly at +-1 (no NaN at large |x|)
__device__ __forceinline__ float tanh_f(float x) { return 1.f - 2.f / (__expf(2.f * x) + 1.f); }

// ---------------- prep kernels ----------------
__global__ void k_prep_weights(const float* __restrict__ Wih, const float* __restrict__ Whh,
                               const float* __restrict__ bih, const float* __restrict__ bhh) {
    int i = blockIdx.x * blockDim.x + threadIdx.x;
    if (i < G4 * HID) {
        g_Wih_h[i] = __float2half_rn(Wih[i]);
        g_Whh_h[i] = __float2half_rn(Whh[i]);
    }
    if (i < G4) g_bsum[i] = bih[i] + bhh[i];
}

// X[t, j, k] = concat(h_self[b,a,256:512], h_inter[b,a,:]) with b=(j>>6)*16+t, a=j&63
__global__ void k_pack_x(const float* __restrict__ h_self, const float* __restrict__ h_inter) {
    int idx = blockIdx.x * blockDim.x + threadIdx.x;   // < TROWS*HID = 2^24
    int t   = idx >> 20;
    int rem = idx & ((1 << 20) - 1);
    int j   = rem >> 9;
    int k   = rem & 511;
    int b   = ((j >> 6) << 4) + t;
    int a   = j & 63;
    float v;
    if (k < NATTN) v = h_self[((size_t)(b * NAg + a)) * (2 * NATTN) + NATTN + k];
    else           v = h_inter[((size_t)(b * NAg + a)) * (HID - NATTN) + (k - NATTN)];
    g_Xh[idx] = __float2half_rn(v);
}

// h0/c0 = hxs[::seq_len], cxs[::seq_len]
__global__ void k_init_state(const float* __restrict__ hxs, const float* __restrict__ cxs) {
    int i = blockIdx.x * blockDim.x + threadIdx.x;     // < BROWS*HID
    int j = i >> 9;
    int k = i & 511;
    int b = (j >> 6) << 4;      // traj*16
    int a = j & 63;
    size_t src = ((size_t)(b * NAg + a)) * HID + k;
    g_hbuf[0][i] = hxs[src];
    g_cbuf[0][i] = cxs[src];
}

// ---------------- big x-path GEMM: Gx = Xh @ Wih^T + bias ----------------
__global__ __launch_bounds__(256) void k_gemm_x() {
    __shared__ __half Asm[128 * AS];
    __shared__ __half Bsm[128 * AS];

    int tid  = threadIdx.x;
    int lane = tid & 31, warp = tid >> 5;
    int wm = warp >> 2, wn = warp & 3;
    int gid = lane >> 2, tig = lane & 3;
    int row0 = blockIdx.y * 128;
    int col0 = blockIdx.x * 128;

    float acc[4][4][4];
#pragma unroll
    for (int a = 0; a < 4; a++)
#pragma unroll
        for (int b = 0; b < 4; b++)
#pragma unroll
            for (int c = 0; c < 4; c++) acc[a][b][c] = 0.f;

    for (int k0 = 0; k0 < HID; k0 += 64) {
#pragma unroll
        for (int i = 0; i < 4; i++) {
            int e = tid + i * 256; int r = e >> 3, c = e & 7;
            *(uint4*)&Asm[r * AS + c * 8] =
                *(const uint4*)&g_Xh[(size_t)(row0 + r) * HID + k0 + c * 8];
        }
#pragma unroll
        for (int i = 0; i < 4; i++) {
            int e = tid + i * 256; int r = e >> 3, c = e & 7;
            *(uint4*)&Bsm[r * AS + c * 8] =
                *(const uint4*)&g_Wih_h[(size_t)(col0 + r) * HID + k0 + c * 8];
        }
        __syncthreads();
#pragma unroll
        for (int kk = 0; kk < 4; kk++) {
            uint32_t af[4][4];
            int cb = kk * 16 + tig * 2;
#pragma unroll
            for (int mi = 0; mi < 4; mi++) {
                int r = wm * 64 + mi * 16 + gid;
                af[mi][0] = *(const uint32_t*)&Asm[r * AS + cb];
                af[mi][1] = *(const uint32_t*)&Asm[(r + 8) * AS + cb];
                af[mi][2] = *(const uint32_t*)&Asm[r * AS + cb + 8];
                af[mi][3] = *(const uint32_t*)&Asm[(r + 8) * AS + cb + 8];
            }
#pragma unroll
            for (int ni = 0; ni < 4; ni++) {
                int n = wn * 32 + ni * 8 + gid;
                uint32_t b0 = *(const uint32_t*)&Bsm[n * AS + cb];
                uint32_t b1 = *(const uint32_t*)&Bsm[n * AS + cb + 8];
#pragma unroll
                for (int mi = 0; mi < 4; mi++) mma16816(acc[mi][ni], af[mi], b0, b1);
            }
        }
        __syncthreads();
    }
#pragma unroll
    for (int mi = 0; mi < 4; mi++)
#pragma unroll
        for (int ni = 0; ni < 4; ni++) {
            int r   = row0 + wm * 64 + mi * 16 + gid;
            int col = col0 + wn * 32 + ni * 8 + tig * 2;
            float b0 = g_bsum[col], b1 = g_bsum[col + 1];
            float2 v0 = make_float2(acc[mi][ni][0] + b0, acc[mi][ni][1] + b1);
            float2 v1 = make_float2(acc[mi][ni][2] + b0, acc[mi][ni][3] + b1);
            *(float2*)&g_Gx[(size_t)r * G4 + col] = v0;
            *(float2*)&g_Gx[(size_t)(r + 8) * G4 + col] = v1;
        }
}

// ---------------- fused recurrent step ----------------
// grid (bu=16 unit-tiles, bm=16 row-tiles). Block C tile: 128 rows x (32 units x 4 gates).
// B tile row rb -> W_hh row (rb>>5)*512 + bu*32 + (rb&31); so Dsm cols: [g*32 + u].
__global__ __launch_bounds__(256) void k_step(int t, const float* __restrict__ reset,
                                              float* __restrict__ out) {
    extern __shared__ char smem_raw[];
    __half* Asm = (__half*)smem_raw;
    __half* Bsm = Asm + 128 * AS;
    float*  Dsm = (float*)smem_raw;        // reused after final sync
    __shared__ float Rs[128];

    const float* hprev = g_hbuf[t & 1];
    const float* cprev = g_cbuf[t & 1];
    float* hnext = g_hbuf[(t + 1) & 1];
    float* cnext = g_cbuf[(t + 1) & 1];

    int tid  = threadIdx.x;
    int lane = tid & 31, warp = tid >> 5;
    int wm = warp >> 2, wn = warp & 3;
    int gid = lane >> 2, tig = lane & 3;
    int row0 = blockIdx.y * 128;
    int bu   = blockIdx.x;

    if (tid < 128) {
        int row = row0 + tid;
        Rs[tid] = 1.f - reset[((row >> 6) << 4) + t];
    }
    __syncthreads();

    float acc[4][4][4];
#pragma unroll
    for (int a = 0; a < 4; a++)
#pragma unroll
        for (int b = 0; b < 4; b++)
#pragma unroll
            for (int c = 0; c < 4; c++) acc[a][b][c] = 0.f;

    for (int k0 = 0; k0 < HID; k0 += 64) {
        // A: reset-scaled fp32 -> fp16 conversion on load
#pragma unroll
        for (int i = 0; i < 8; i++) {
            int e = tid + i * 256;            // 0..2047 float4 slots
            int r = e >> 4, c4 = e & 15;
            float4 v = *(const float4*)&hprev[(size_t)(row0 + r) * HID + k0 + c4 * 4];
            float s = Rs[r];
            __half2 p0 = __floats2half2_rn(v.x * s, v.y * s);
            __half2 p1 = __floats2half2_rn(v.z * s, v.w * s);
            *(__half2*)&Asm[r * AS + c4 * 4]     = p0;
            *(__half2*)&Asm[r * AS + c4 * 4 + 2] = p1;
        }
        // B: gate-interleaved W_hh rows (fp16 pre-converted)
#pragma unroll
        for (int i = 0; i < 4; i++) {
            int e = tid + i * 256;            // 0..1023 uint4 slots
            int rb = e >> 3, c = e & 7;
            int wr = ((rb >> 5) << 9) + (bu << 5) + (rb & 31);
            *(uint4*)&Bsm[rb * AS + c * 8] =
                *(const uint4*)&g_Whh_h[(size_t)wr * HID + k0 + c * 8];
        }
        __syncthreads();
#pragma unroll
        for (int kk = 0; kk < 4; kk++) {
            uint32_t af[4][4];
            int cb = kk * 16 + tig * 2;
#pragma unroll
            for (int mi = 0; mi < 4; mi++) {
                int r = wm * 64 + mi * 16 + gid;
                af[mi][0] = *(const uint32_t*)&Asm[r * AS + cb];
                af[mi][1] = *(const uint32_t*)&Asm[(r + 8) * AS + cb];
                af[mi][2] = *(const uint32_t*)&Asm[r * AS + cb + 8];
                af[mi][3] = *(const uint32_t*)&Asm[(r + 8) * AS + cb + 8];
            }
#pragma unroll
            for (int ni = 0; ni < 4; ni++) {
                int n = wn * 32 + ni * 8 + gid;
                uint32_t b0 = *(const uint32_t*)&Bsm[n * AS + cb];
                uint32_t b1 = *(const uint32_t*)&Bsm[n * AS + cb + 8];
#pragma unroll
                for (int mi = 0; mi < 4; mi++) mma16816(acc[mi][ni], af[mi], b0, b1);
            }
        }
        __syncthreads();
    }

    // spill D to smem so each thread can gather all 4 gates of a unit
#pragma unroll
    for (int mi = 0; mi < 4; mi++)
#pragma unroll
        for (int ni = 0; ni < 4; ni++) {
            int r   = wm * 64 + mi * 16 + gid;
            int col = wn * 32 + ni * 8 + tig * 2;
            *(float2*)&Dsm[r * DS + col]       = make_float2(acc[mi][ni][0], acc[mi][ni][1]);
            *(float2*)&Dsm[(r + 8) * DS + col] = make_float2(acc[mi][ni][2], acc[mi][ni][3]);
        }
    __syncthreads();

    const float* GxT  = &g_Gx[(size_t)(t * BROWS) * G4];
    float* out_h = out;
    float* out_c = out + (size_t)OUTHALF;
#pragma unroll
    for (int i = 0; i < 16; i++) {
        int e = tid + i * 256;                // 0..4095 = 128 rows x 32 units
        int r = e >> 5, u = e & 31;
        int row = row0 + r;
        int U   = (bu << 5) + u;
        size_t gb = (size_t)row * G4 + U;
        float xi = Dsm[r * DS + u]        + GxT[gb];
        float xf = Dsm[r * DS + 32 + u]   + GxT[gb + 512];
        float xg = Dsm[r * DS + 64 + u]   + GxT[gb + 1024];
        float xo = Dsm[r * DS + 96 + u]   + GxT[gb + 1536];
        float ii = sigmoid_f(xi);
        float ff = sigmoid_f(xf);
        float gg = tanh_f(xg);
        float oo = sigmoid_f(xo);
        float cc = cprev[(size_t)row * HID + U] * Rs[r];
        float c2 = ff * cc + ii * gg;
        float h2 = oo * tanh_f(c2);
        hnext[(size_t)row * HID + U] = h2;
        cnext[(size_t)row * HID + U] = c2;
        int b = ((row >> 6) << 4) + t;
        int a = row & 63;
        size_t oidx = ((size_t)(b * NAg + a)) * HID + U;
        out_h[oidx] = h2;
        out_c[oidx] = c2;
    }
}

// ---------------- launch ----------------
extern "C" void kernel_launch(void* const* d_in, const int* in_sizes, int n_in,
                              void* d_out, int out_size) {
    const float* h_self  = (const float*)d_in[0];
    const float* h_inter = (const float*)d_in[1];
    const float* hxs     = (const float*)d_in[2];
    const float* cxs     = (const float*)d_in[3];
    const float* reset   = (const float*)d_in[4];
    const float* Wih     = (const float*)d_in[5];
    const float* Whh     = (const float*)d_in[6];
    const float* bih     = (const float*)d_in[7];
    const float* bhh     = (const float*)d_in[8];
    float* out = (float*)d_out;

    const int step_smem = 128 * DS * 4;     // 67584 B (Dsm dominates the A/B tiles)
    cudaFuncSetAttribute(k_step, cudaFuncAttributeMaxDynamicSharedMemorySize, step_smem);

    k_prep_weights<<<4096, 256>>>(Wih, Whh, bih, bhh);
    k_pack_x<<<65536, 256>>>(h_self, h_inter);
    k_init_state<<<4096, 256>>>(hxs, cxs);
    k_gemm_x<<<dim3(16, 256), 256>>>();
    for (int t = 0; t < SEQ; t++)
        k_step<<<dim3(16, 16), 256, step_smem>>>(t, reset, out);
}

// round 3
// speedup vs baseline: 1.2432x; 1.2432x over previous
#include <cuda_runtime.h>
#include <cuda_fp16.h>
#include <cstdint>

// ---------------- problem constants ----------------
#define HID   512
#define G4    2048
#define NAg   64
#define SEQ   16
#define BROWS 2048         // rows per timestep (32 traj * 64 agents)
#define TROWS 32768        // SEQ*BROWS
#define NATTN 256
#define OUTHALF 16777216   // 512*64*512

#define AS 72              // smem tile row stride (halves)
#define DS 132             // Dsm row stride (floats)
#define TILE (128*AS)      // halves per stage tile

// ---------------- device scratch ----------------
__device__ __half g_Wih_h[G4 * HID];
__device__ __half g_Whh_h[G4 * HID];
__device__ float  g_bsum[G4];
__device__ __half g_Xh[(size_t)TROWS * HID];          // packed time-major x (fp16)
__device__ __half g_Gx[(size_t)TROWS * G4];           // precomputed x-gates (fp16)
__device__ __half g_h16[2][BROWS * HID];              // h carry, fp16, pre-reset-scaled
__device__ float  g_c0[BROWS * HID];                  // initial c (pre-scaled by 1-r0)
__device__ unsigned g_bar[16];                        // per-row-group barrier counters

// ---------------- helpers ----------------
__device__ __forceinline__ void mma16816(float* d, const uint32_t* a, uint32_t b0, uint32_t b1) {
    asm volatile(
        "mma.sync.aligned.m16n8k16.row.col.f32.f16.f16.f32 "
        "{%0,%1,%2,%3},{%4,%5,%6,%7},{%8,%9},{%0,%1,%2,%3};\n"
        : "+f"(d[0]), "+f"(d[1]), "+f"(d[2]), "+f"(d[3])
        : "r"(a[0]), "r"(a[1]), "r"(a[2]), "r"(a[3]), "r"(b0), "r"(b1));
}
__device__ __forceinline__ float sigmoid_f(float x) { return 1.f / (1.f + __expf(-x)); }
__device__ __forceinline__ float tanh_f(float x) { return 1.f - 2.f / (__expf(2.f * x) + 1.f); }

__device__ __forceinline__ uint32_t smaddr(const void* p) {
    return (uint32_t)__cvta_generic_to_shared(p);
}
// L1-cached copy: ONLY for data not mutated since the last kernel-launch boundary.
__device__ __forceinline__ void cpa16(uint32_t d, const void* s) {
    asm volatile("cp.async.ca.shared.global [%0], [%1], 16;\n" :: "r"(d), "l"(s));
}
// L2-only copy: required for cross-block-mutated data inside the persistent kernel
// (L1 has no cross-SM coherence and is only flushed per launch).
__device__ __forceinline__ void cpa16_cg(uint32_t d, const void* s) {
    asm volatile("cp.async.cg.shared.global [%0], [%1], 16;\n" :: "r"(d), "l"(s));
}
#define CP_COMMIT asm volatile("cp.async.commit_group;\n")
#define CP_WAIT1  asm volatile("cp.async.wait_group 1;\n")
#define CP_WAIT0  asm volatile("cp.async.wait_group 0;\n")

__device__ __forceinline__ void mma_tile(const __half* Asm, const __half* Bsm,
                                         float acc[4][4][4], int wm, int wn, int gid, int tig) {
#pragma unroll
    for (int kk = 0; kk < 4; kk++) {
        uint32_t af[4][4];
        int cb = kk * 16 + tig * 2;
#pragma unroll
        for (int mi = 0; mi < 4; mi++) {
            int r = wm * 64 + mi * 16 + gid;
            af[mi][0] = *(const uint32_t*)&Asm[r * AS + cb];
            af[mi][1] = *(const uint32_t*)&Asm[(r + 8) * AS + cb];
            af[mi][2] = *(const uint32_t*)&Asm[r * AS + cb + 8];
            af[mi][3] = *(const uint32_t*)&Asm[(r + 8) * AS + cb + 8];
        }
#pragma unroll
        for (int ni = 0; ni < 4; ni++) {
            int n = wn * 32 + ni * 8 + gid;
            uint32_t b0 = *(const uint32_t*)&Bsm[n * AS + cb];
            uint32_t b1 = *(const uint32_t*)&Bsm[n * AS + cb + 8];
#pragma unroll
            for (int mi = 0; mi < 4; mi++) mma16816(acc[mi][ni], af[mi], b0, b1);
        }
    }
}

// ---------------- prep kernels ----------------
__global__ void k_prep_weights(const float* __restrict__ Wih, const float* __restrict__ Whh,
                               const float* __restrict__ bih, const float* __restrict__ bhh) {
    int i = blockIdx.x * blockDim.x + threadIdx.x;
    if (i < G4 * HID) {
        g_Wih_h[i] = __float2half_rn(Wih[i]);
        g_Whh_h[i] = __float2half_rn(Whh[i]);
    }
    if (i < G4) g_bsum[i] = bih[i] + bhh[i];
}

__global__ void k_pack_x(const float* __restrict__ h_self, const float* __restrict__ h_inter) {
    int idx = blockIdx.x * blockDim.x + threadIdx.x;   // < TROWS*HID = 2^24
    int t   = idx >> 20;
    int rem = idx & ((1 << 20) - 1);
    int j   = rem >> 9;
    int k   = rem & 511;
    int b   = ((j >> 6) << 4) + t;
    int a   = j & 63;
    float v;
    if (k < NATTN) v = h_self[((size_t)(b * NAg + a)) * (2 * NATTN) + NATTN + k];
    else           v = h_inter[((size_t)(b * NAg + a)) * (HID - NATTN) + (k - NATTN)];
    g_Xh[idx] = __float2half_rn(v);
}

// h0 = hxs[::seq], c0 = cxs[::seq], both pre-scaled by (1-r0); zero barrier counters.
__global__ void k_init_state(const float* __restrict__ hxs, const float* __restrict__ cxs,
                             const float* __restrict__ reset) {
    int i = blockIdx.x * blockDim.x + threadIdx.x;     // < BROWS*HID (exact)
    int j = i >> 9;
    int k = i & 511;
    int b = (j >> 6) << 4;
    int a = j & 63;
    size_t src = ((size_t)(b * NAg + a)) * HID + k;
    float rs = 1.f - reset[b];
    g_h16[0][i] = __float2half_rn(hxs[src] * rs);
    g_c0[i] = cxs[src] * rs;
    if (blockIdx.x == 0 && threadIdx.x < 16) g_bar[threadIdx.x] = 0;
}

// ---------------- x-path GEMM: Gx = Xh @ Wih^T + bias (fp16 out, cp.async pipelined) ----
__global__ __launch_bounds__(256, 2) void k_gemm_x() {
    extern __shared__ __half sm[];   // [4*TILE]: A0,A1,B0,B1
    int tid  = threadIdx.x;
    int lane = tid & 31, warp = tid >> 5;
    int wm = warp >> 2, wn = warp & 3;
    int gid = lane >> 2, tig = lane & 3;
    int row0 = blockIdx.y * 128;
    int col0 = blockIdx.x * 128;

    float acc[4][4][4];
#pragma unroll
    for (int a = 0; a < 4; a++)
#pragma unroll
        for (int b = 0; b < 4; b++)
#pragma unroll
            for (int c = 0; c < 4; c++) acc[a][b][c] = 0.f;

    auto load = [&](int k0, int s) {
#pragma unroll
        for (int i = 0; i < 4; i++) {
            int e = tid + i * 256; int r = e >> 3, c = e & 7;
            cpa16(smaddr(&sm[s * TILE + r * AS + c * 8]),
                  &g_Xh[(size_t)(row0 + r) * HID + k0 + c * 8]);
        }
#pragma unroll
        for (int i = 0; i < 4; i++) {
            int e = tid + i * 256; int r = e >> 3, c = e & 7;
            cpa16(smaddr(&sm[(2 + s) * TILE + r * AS + c * 8]),
                  &g_Wih_h[(size_t)(col0 + r) * HID + k0 + c * 8]);
        }
    };

    load(0, 0); CP_COMMIT;
    for (int it = 0; it < 8; it++) {
        int s = it & 1;
        if (it < 7) { load((it + 1) * 64, s ^ 1); CP_COMMIT; CP_WAIT1; }
        else        { CP_WAIT0; }
        __syncthreads();
        mma_tile(&sm[s * TILE], &sm[(2 + s) * TILE], acc, wm, wn, gid, tig);
        __syncthreads();
    }

#pragma unroll
    for (int mi = 0; mi < 4; mi++)
#pragma unroll
        for (int ni = 0; ni < 4; ni++) {
            int r   = row0 + wm * 64 + mi * 16 + gid;
            int col = col0 + wn * 32 + ni * 8 + tig * 2;
            float b0 = g_bsum[col], b1 = g_bsum[col + 1];
            *(__half2*)&g_Gx[(size_t)r * G4 + col] =
                __floats2half2_rn(acc[mi][ni][0] + b0, acc[mi][ni][1] + b1);
            *(__half2*)&g_Gx[(size_t)(r + 8) * G4 + col] =
                __floats2half2_rn(acc[mi][ni][2] + b0, acc[mi][ni][3] + b1);
        }
}

// ---------------- persistent recurrent scan ----------------
// grid (bu=16, bm=16) = 256 blocks, all co-resident (2/SM, 296 slots >= 256 -> one wave).
// Each block owns C-tile [128 rows x 32 units] across all 16 steps: c carry in smem.
// h carry through gmem (fp16, pre-scaled by next reset); the 16 bu-blocks of a row-group
// sync via a monotonic per-bm counter (groups drift independently).
__global__ __launch_bounds__(256, 2) void k_steps(const float* __restrict__ reset,
                                                  float* __restrict__ out) {
    extern __shared__ char smraw[];
    __half* sm  = (__half*)smraw;                       // 4*TILE halves (stages)
    float*  Dsm = (float*)smraw;                        // overlaps stages (post-mainloop)
    float*  Csm = (float*)(smraw + 4 * TILE * 2);       // 128*32 floats
    float*  Rn  = (float*)(smraw + 4 * TILE * 2 + 128 * 32 * 4);  // 128 floats

    int tid  = threadIdx.x;
    int lane = tid & 31, warp = tid >> 5;
    int wm = warp >> 2, wn = warp & 3;
    int gid = lane >> 2, tig = lane & 3;
    int bu   = blockIdx.x;
    int bm   = blockIdx.y;
    int row0 = bm * 128;

    // init block-private c carry (thread-private slots; no sync needed)
#pragma unroll
    for (int i = 0; i < 16; i++) {
        int e = tid + i * 256;
        Csm[e] = g_c0[(size_t)(row0 + (e >> 5)) * HID + (bu << 5) + (e & 31)];
    }

    float* out_h = out;
    float* out_c = out + (size_t)OUTHALF;

    for (int t = 0; t < SEQ; t++) {
        if (tid < 128) {
            int row = row0 + tid;
            float r = (t + 1 < SEQ) ? reset[((row >> 6) << 4) + t + 1] : 0.f;
            Rn[tid] = 1.f - r;
        }

        float acc[4][4][4];
#pragma unroll
        for (int a = 0; a < 4; a++)
#pragma unroll
            for (int b = 0; b < 4; b++)
#pragma unroll
                for (int c = 0; c < 4; c++) acc[a][b][c] = 0.f;

        const __half* hsrc = g_h16[t & 1];
        auto load = [&](int k0, int s) {
#pragma unroll
            for (int i = 0; i < 4; i++) {
                int e = tid + i * 256; int r = e >> 3, c = e & 7;
                // .cg: h is mutated by other blocks within this launch -> bypass L1
                cpa16_cg(smaddr(&sm[s * TILE + r * AS + c * 8]),
                         &hsrc[(size_t)(row0 + r) * HID + k0 + c * 8]);
            }
#pragma unroll
            for (int i = 0; i < 4; i++) {
                int e = tid + i * 256; int rb = e >> 3, c = e & 7;
                int wr = ((rb >> 5) << 9) + (bu << 5) + (rb & 31);   // gate-interleaved
                cpa16(smaddr(&sm[(2 + s) * TILE + rb * AS + c * 8]),
                      &g_Whh_h[(size_t)wr * HID + k0 + c * 8]);
            }
        };

        load(0, 0); CP_COMMIT;
        for (int it = 0; it < 8; it++) {
            int s = it & 1;
            if (it < 7) { load((it + 1) * 64, s ^ 1); CP_COMMIT; CP_WAIT1; }
            else        { CP_WAIT0; }
            __syncthreads();
            mma_tile(&sm[s * TILE], &sm[(2 + s) * TILE], acc, wm, wn, gid, tig);
            __syncthreads();
        }

        // spill D to smem so each thread gathers all 4 gates of one unit
#pragma unroll
        for (int mi = 0; mi < 4; mi++)
#pragma unroll
            for (int ni = 0; ni < 4; ni++) {
                int r   = wm * 64 + mi * 16 + gid;
                int col = wn * 32 + ni * 8 + tig * 2;
                *(float2*)&Dsm[r * DS + col]       = make_float2(acc[mi][ni][0], acc[mi][ni][1]);
                *(float2*)&Dsm[(r + 8) * DS + col] = make_float2(acc[mi][ni][2], acc[mi][ni][3]);
            }
        __syncthreads();

        const __half* GxT = g_Gx + (size_t)t * BROWS * G4;
        __half* hnx = g_h16[(t + 1) & 1];
#pragma unroll
        for (int i = 0; i < 16; i++) {
            int e = tid + i * 256;
            int r = e >> 5, u = e & 31;
            int row = row0 + r;
            int U   = (bu << 5) + u;
            size_t gb = (size_t)row * G4 + U;
            float xi = Dsm[r * DS + u]      + __half2float(GxT[gb]);
            float xf = Dsm[r * DS + 32 + u] + __half2float(GxT[gb + 512]);
            float xg = Dsm[r * DS + 64 + u] + __half2float(GxT[gb + 1024]);
            float xo = Dsm[r * DS + 96 + u] + __half2float(GxT[gb + 1536]);
            float ii = sigmoid_f(xi);
            float ff = sigmoid_f(xf);
            float gg = tanh_f(xg);
            float oo = sigmoid_f(xo);
            float c2 = ff * Csm[e] + ii * gg;
            float h2 = oo * tanh_f(c2);
            int b = ((row >> 6) << 4) + t;
            int a = row & 63;
            size_t oidx = ((size_t)(b * NAg + a)) * HID + U;
            out_h[oidx] = h2;
            out_c[oidx] = c2;
            float rn = Rn[r];
            Csm[e] = c2 * rn;                                       // carry c (pre-scaled)
            hnx[(size_t)row * HID + U] = __float2half_rn(h2 * rn);  // carry h (pre-scaled)
        }

        // group barrier among the 16 bu-blocks of this row-group
        if (t < SEQ - 1) {
            __syncthreads();
            if (tid == 0) {
                __threadfence();                     // release: publish h writes
                atomicAdd(&g_bar[bm], 1u);
                unsigned target = 16u * (unsigned)(t + 1);
                while (atomicAdd(&g_bar[bm], 0u) < target) { __nanosleep(64); }
                __threadfence();                     // acquire: order next step's loads
            }
            __syncthreads();
        }
    }
}

// ---------------- launch ----------------
extern "C" void kernel_launch(void* const* d_in, const int* in_sizes, int n_in,
                              void* d_out, int out_size) {
    const float* h_self  = (const float*)d_in[0];
    const float* h_inter = (const float*)d_in[1];
    const float* hxs     = (const float*)d_in[2];
    const float* cxs     = (const float*)d_in[3];
    const float* reset   = (const float*)d_in[4];
    const float* Wih     = (const float*)d_in[5];
    const float* Whh     = (const float*)d_in[6];
    const float* bih     = (const float*)d_in[7];
    const float* bhh     = (const float*)d_in[8];
    float* out = (float*)d_out;

    const int gemm_smem = 4 * TILE * 2;                          // 73728 B
    const int step_smem = 4 * TILE * 2 + 128 * 32 * 4 + 512;     // 90624 B
    cudaFuncSetAttribute(k_gemm_x, cudaFuncAttributeMaxDynamicSharedMemorySize, gemm_smem);
    cudaFuncSetAttribute(k_steps,  cudaFuncAttributeMaxDynamicSharedMemorySize, step_smem);

    k_prep_weights<<<4096, 256>>>(Wih, Whh, bih, bhh);
    k_pack_x<<<65536, 256>>>(h_self, h_inter);
    k_init_state<<<4096, 256>>>(hxs, cxs, reset);
    k_gemm_x<<<dim3(16, 256), 256, gemm_smem>>>();
    k_steps<<<dim3(16, 16), 256, step_smem>>>(reset, out);
}